// round 5
// baseline (speedup 1.0000x reference)
#include <cuda_runtime.h>
#include <cuda_bf16.h>

// out[b,l,g,o] = sum_k mask(b,l,k) * sum_i X[b,l+k-2,g*64+i] * W[g,o,i,k]
// mask(l,k) = (pos[l+k-2]-(l+k-2) == pos[l]-l); X zero-padded outside [0,L).
// mma.sync bf16 3-pass hi/lo split (AhBh + AlBh + AhBl), fp32 accumulate.
// Barrier-free mainloop: all W slices resident in smem, masks in registers.

constexpr int Bb = 4, Ll = 4096, Cc = 1024, Gg = 16, IPG = 64, OPG = 64, KK = 5, TL = 128;
constexpr int A_ROWS = TL + 4;    // 132

// pre-split W: [g][k][o][i] bf16 hi / lo
__device__ __nv_bfloat16 g_Whi[Gg * KK * OPG * IPG];
__device__ __nv_bfloat16 g_Wlo[Gg * KK * OPG * IPG];

// smem layout (bytes); every region base is 128B-aligned
constexpr int SA_H  = 0;                       // A hi: 132 x 128B = 16896
constexpr int SA_L  = A_ROWS * 128;            // 16896: A lo
constexpr int SW    = 2 * A_ROWS * 128;        // 33792: W, 5 slices x (hi 8K + lo 8K)
constexpr int W_LO  = 8192;
constexpr int W_SLICE = 16384;
constexpr int SMEM_BYTES = SW + KK * W_SLICE;  // 115712 -> 2 CTAs/SM (with 1KB reserve)

__device__ __forceinline__ unsigned smem_u32(const void* p) {
    unsigned a;
    asm("{ .reg .u64 t; cvta.to.shared.u64 t, %1; cvt.u32.u64 %0, t; }" : "=r"(a) : "l"(p));
    return a;
}
__device__ __forceinline__ unsigned sw128(unsigned off) { return off ^ ((off >> 3) & 0x70); }

// f32 pair -> packed bf16 hi + packed bf16 lo (residual)
__device__ __forceinline__ void hilo2(float a, float b, unsigned& h, unsigned& l) {
    asm("cvt.rn.bf16x2.f32 %0, %1, %2;" : "=r"(h) : "f"(b), "f"(a));   // {hi:b, lo:a}
    float ha = __uint_as_float(h << 16);
    float hb = __uint_as_float(h & 0xffff0000u);
    float la = a - ha, lb = b - hb;
    asm("cvt.rn.bf16x2.f32 %0, %1, %2;" : "=r"(l) : "f"(lb), "f"(la));
}

__device__ __forceinline__ void sts64(unsigned addr, unsigned r0, unsigned r1) {
    asm volatile("st.shared.v2.b32 [%0], {%1, %2};" :: "r"(addr), "r"(r0), "r"(r1) : "memory");
}
__device__ __forceinline__ void ldsm4(unsigned addr, unsigned& r0, unsigned& r1,
                                      unsigned& r2, unsigned& r3) {
    asm volatile("ldmatrix.sync.aligned.m8n8.x4.shared.b16 {%0, %1, %2, %3}, [%4];"
                 : "=r"(r0), "=r"(r1), "=r"(r2), "=r"(r3) : "r"(addr));
}
__device__ __forceinline__ void mma16816(float* c,
                                         unsigned a0, unsigned a1, unsigned a2, unsigned a3,
                                         unsigned b0, unsigned b1) {
    asm volatile("mma.sync.aligned.m16n8k16.row.col.f32.bf16.bf16.f32 "
                 "{%0,%1,%2,%3}, {%4,%5,%6,%7}, {%8,%9}, {%0,%1,%2,%3};"
                 : "+f"(c[0]), "+f"(c[1]), "+f"(c[2]), "+f"(c[3])
                 : "r"(a0), "r"(a1), "r"(a2), "r"(a3), "r"(b0), "r"(b1));
}
__device__ __forceinline__ void cp16(unsigned dst, const void* src) {
    asm volatile("cp.async.cg.shared.global [%0], [%1], 16;" :: "r"(dst), "l"(src) : "memory");
}

// ---- pre-kernel: W (g,o,i,k) f32 -> (g,k,o,i) bf16 hi/lo ----
__global__ void prep_w(const float* __restrict__ w) {
    int idx = blockIdx.x * 256 + threadIdx.x;
    if (idx >= Gg * KK * OPG * IPG) return;
    int i = idx & 63;
    int r = idx >> 6;
    int o = r & 63;
    int r2 = r >> 6;
    int k = r2 % KK;
    int g = r2 / KK;
    float v = w[(((g * OPG + o) * IPG + i) * KK) + k];
    __nv_bfloat16 hb = __float2bfloat16(v);
    __nv_bfloat16 lb = __float2bfloat16(v - __bfloat162float(hb));
    g_Whi[idx] = hb;
    g_Wlo[idx] = lb;
}

__global__ __launch_bounds__(128, 2)
void masked_conv1d_hmma(const float* __restrict__ x,
                        const int*   __restrict__ pos,
                        float*       __restrict__ out) {
    extern __shared__ char sm[];
    const unsigned smb = smem_u32(sm);
    const int l0 = blockIdx.x * TL, g = blockIdx.y, b = blockIdx.z;
    const int tid = threadIdx.x;
    const int wid = tid >> 5, lane = tid & 31;

    // ---- stage ALL W slices (hi+lo) via cp.async, one group ----
    {
        const char* wh = (const char*)(g_Whi + (size_t)g * (KK * OPG * IPG));
        const char* wl = (const char*)(g_Wlo + (size_t)g * (KK * OPG * IPG));
#pragma unroll
        for (int t = 0; t < 20; t++) {
            int ch = tid + t * 128;                   // 0..2559 16B chunks
            int k = ch >> 9, c = ch & 511;
            unsigned dst = smb + SW + k * W_SLICE + sw128((unsigned)c * 16);
            cp16(dst, wh + (size_t)ch * 16);
            cp16(dst + W_LO, wl + (size_t)ch * 16);
        }
        asm volatile("cp.async.commit_group;" ::: "memory");
    }

    const int lane8 = lane & 7, seg = lane >> 3;
    const int rbase = wid * 32 + (lane >> 2);        // this thread's base output row

    // ---- per-thread mask bits: bit(ci*5+k) = mask(row rbase+ci*8, conv-k) ----
    unsigned mbits = 0;
    {
        const int* pb = pos + b * Ll;
#pragma unroll
        for (int ci = 0; ci < 4; ci++) {
            int base = rbase + ci * 8;
            int glc = l0 + base;                      // center row, always in [0,Ll)
            int center = pb[glc] - glc;
#pragma unroll
            for (int k = 0; k < KK; k++) {
                int gl = l0 + base + k - 2;
                int d = (gl >= 0 && gl < Ll) ? (pb[gl] - gl) : 0x40000000;
                if (d == center) mbits |= 1u << (ci * 5 + k);
            }
        }
    }

    // ---- stage X tile: f32 -> bf16 hi/lo, swizzled 128B rows ----
    const float* xg = x + (size_t)b * Ll * Cc + g * IPG;
    for (int idx = tid; idx < A_ROWS * 16; idx += 128) {
        int j  = idx >> 4;
        int i4 = idx & 15;
        int gl = l0 - 2 + j;
        float4 v = make_float4(0.f, 0.f, 0.f, 0.f);
        if (gl >= 0 && gl < Ll)
            v = *(const float4*)(xg + (size_t)gl * Cc + i4 * 4);
        unsigned h0, h1, e0, e1;
        hilo2(v.x, v.y, h0, e0);
        hilo2(v.z, v.w, h1, e1);
        unsigned sw = sw128((unsigned)(j * 128 + i4 * 8));
        sts64(smb + SA_H + sw, h0, h1);
        sts64(smb + SA_L + sw, e0, e1);
    }

    asm volatile("cp.async.wait_group 0;" ::: "memory");
    __syncthreads();                                  // the ONLY barrier

    // ---- accumulators: 2 M-tiles x 8 N-tiles x 4 ----
    float c[2][8][4];
#pragma unroll
    for (int mt = 0; mt < 2; mt++)
#pragma unroll
        for (int nt = 0; nt < 8; nt++)
#pragma unroll
            for (int e = 0; e < 4; e++) c[mt][nt][e] = 0.f;

    const unsigned acoff = (unsigned)((seg >> 1) << 3);
    const unsigned brow  = (unsigned)(lane8 + ((seg >> 1) << 3));
    const unsigned bcoff = (unsigned)((seg & 1) << 3);

#pragma unroll
    for (int k = 0; k < KK; k++) {
        const unsigned bbase = smb + SW + k * W_SLICE;
        const bool m0 = (mbits >> (0 * 5 + k)) & 1;
        const bool m1 = (mbits >> (1 * 5 + k)) & 1;
        const bool m2 = (mbits >> (2 * 5 + k)) & 1;
        const bool m3 = (mbits >> (3 * 5 + k)) & 1;

        const unsigned arow0 = (unsigned)(wid * 32 + k + lane8 + ((seg & 1) << 3));

#pragma unroll
        for (int q = 0; q < 4; q++) {                  // 16-wide i-chunks
            unsigned ah[8], al[8];
            unsigned a0 = smb + SA_H + sw128(arow0 * 128 + (q * 16 + acoff) * 2);
            unsigned a1 = smb + SA_H + sw128((arow0 + 16) * 128 + (q * 16 + acoff) * 2);
            ldsm4(a0, ah[0], ah[1], ah[2], ah[3]);
            ldsm4(a1, ah[4], ah[5], ah[6], ah[7]);
            ldsm4(a0 + (SA_L - SA_H), al[0], al[1], al[2], al[3]);
            ldsm4(a1 + (SA_L - SA_H), al[4], al[5], al[6], al[7]);
            // row-granular mask
            ah[0] = m0 ? ah[0] : 0u;  ah[2] = m0 ? ah[2] : 0u;
            ah[1] = m1 ? ah[1] : 0u;  ah[3] = m1 ? ah[3] : 0u;
            ah[4] = m2 ? ah[4] : 0u;  ah[6] = m2 ? ah[6] : 0u;
            ah[5] = m3 ? ah[5] : 0u;  ah[7] = m3 ? ah[7] : 0u;
            al[0] = m0 ? al[0] : 0u;  al[2] = m0 ? al[2] : 0u;
            al[1] = m1 ? al[1] : 0u;  al[3] = m1 ? al[3] : 0u;
            al[4] = m2 ? al[4] : 0u;  al[6] = m2 ? al[6] : 0u;
            al[5] = m3 ? al[5] : 0u;  al[7] = m3 ? al[7] : 0u;

#pragma unroll
            for (int p = 0; p < 4; p++) {              // pairs of N-tiles
                unsigned baddr = bbase + sw128((p * 16 + brow) * 128 + (q * 16 + bcoff) * 2);
                unsigned bh0, bh1, bh2, bh3, bl0, bl1, bl2, bl3;
                ldsm4(baddr, bh0, bh1, bh2, bh3);
                ldsm4(baddr + W_LO, bl0, bl1, bl2, bl3);
#pragma unroll
                for (int mt = 0; mt < 2; mt++) {
                    mma16816(c[mt][p*2],   ah[mt*4], ah[mt*4+1], ah[mt*4+2], ah[mt*4+3], bh0, bh1);
                    mma16816(c[mt][p*2+1], ah[mt*4], ah[mt*4+1], ah[mt*4+2], ah[mt*4+3], bh2, bh3);
                    mma16816(c[mt][p*2],   al[mt*4], al[mt*4+1], al[mt*4+2], al[mt*4+3], bh0, bh1);
                    mma16816(c[mt][p*2+1], al[mt*4], al[mt*4+1], al[mt*4+2], al[mt*4+3], bh2, bh3);
                    mma16816(c[mt][p*2],   ah[mt*4], ah[mt*4+1], ah[mt*4+2], ah[mt*4+3], bl0, bl1);
                    mma16816(c[mt][p*2+1], ah[mt*4], ah[mt*4+1], ah[mt*4+2], ah[mt*4+3], bl2, bl3);
                }
            }
        }
    }

    // ---- epilogue: fragments -> out (B,L,G,OPG) ----
    const int ocol = (lane & 3) * 2;
#pragma unroll
    for (int mt = 0; mt < 2; mt++) {
        const int row0 = l0 + wid * 32 + mt * 16 + (lane >> 2);
        float* o0 = out + (((size_t)b * Ll + row0) * Gg + g) * OPG + ocol;
        float* o1 = o0 + (size_t)8 * Gg * OPG;
#pragma unroll
        for (int nt = 0; nt < 8; nt++) {
            *(float2*)(o0 + nt * 8) = make_float2(c[mt][nt][0], c[mt][nt][1]);
            *(float2*)(o1 + nt * 8) = make_float2(c[mt][nt][2], c[mt][nt][3]);
        }
    }
}

extern "C" void kernel_launch(void* const* d_in, const int* in_sizes, int n_in,
                              void* d_out, int out_size) {
    const float* x   = (const float*)d_in[0];
    const int*   pos = (const int*)d_in[1];
    const float* w   = (const float*)d_in[2];
    float*       out = (float*)d_out;

    prep_w<<<(Gg * KK * OPG * IPG + 255) / 256, 256>>>(w);

    cudaFuncSetAttribute(masked_conv1d_hmma,
                         cudaFuncAttributeMaxDynamicSharedMemorySize, SMEM_BYTES);
    dim3 grid(Ll / TL, Gg, Bb);   // (32, 16, 4)
    masked_conv1d_hmma<<<grid, 128, SMEM_BYTES>>>(x, pos, out);
}

// round 6
// speedup vs baseline: 1.5164x; 1.5164x over previous
#include <cuda_runtime.h>
#include <cuda_fp16.h>

// out[b,l,g,o] = sum_k mask(b,l,k) * sum_i X[b,l+k-2,g*64+i] * W[g,o,i,k]
// mask(l,k) = (pos[l+k-2]-(l+k-2) == pos[l]-l); X zero-padded outside [0,L).
// fp16 2-pass: X split hi/lo fp16, W rounded once to fp16.
//   out ~= Xh*Wh + Xl*Wh   (error = X*Wl ~ 2^-12 rel, fp32 accumulate)
// mma.sync m16n8k16 f32.f16.f16.f32; warp tile M=32xN=64; 4 CTAs/SM.

constexpr int Bb = 4, Ll = 4096, Cc = 1024, Gg = 16, IPG = 64, OPG = 64, KK = 5, TL = 128;
constexpr int A_ROWS = TL + 4;    // 132

// pre-rounded W: [g][k][o][i] fp16
__device__ __half g_Wh[Gg * KK * OPG * IPG];

// smem layout (bytes); 128B rows, SW128 swizzled
constexpr int SA_H  = 0;                       // A hi: 132 x 128B = 16896
constexpr int SA_L  = A_ROWS * 128;            // A lo
constexpr int SB    = 2 * A_ROWS * 128;        // 33792: W double buffer
constexpr int B_BUF = 8192;                    // one k-slice (64x64 fp16)
constexpr int SMEM_BYTES = SB + 2 * B_BUF;     // 50176 -> 4 CTAs/SM

__device__ __forceinline__ unsigned smem_u32(const void* p) {
    unsigned a;
    asm("{ .reg .u64 t; cvta.to.shared.u64 t, %1; cvt.u32.u64 %0, t; }" : "=r"(a) : "l"(p));
    return a;
}
__device__ __forceinline__ unsigned sw128(unsigned off) { return off ^ ((off >> 3) & 0x70); }

// f32 pair -> packed fp16 hi + packed fp16 lo (residual)
__device__ __forceinline__ void hilo2h(float a, float b, unsigned& h, unsigned& l) {
    asm("cvt.rn.f16x2.f32 %0, %1, %2;" : "=r"(h) : "f"(b), "f"(a));   // {lo:a, hi:b}
    __half2 hh = *reinterpret_cast<__half2*>(&h);
    float la = a - __half2float(__low2half(hh));
    float lb = b - __half2float(__high2half(hh));
    asm("cvt.rn.f16x2.f32 %0, %1, %2;" : "=r"(l) : "f"(lb), "f"(la));
}

__device__ __forceinline__ void sts64(unsigned addr, unsigned r0, unsigned r1) {
    asm volatile("st.shared.v2.b32 [%0], {%1, %2};" :: "r"(addr), "r"(r0), "r"(r1) : "memory");
}
__device__ __forceinline__ void ldsm4(unsigned addr, unsigned& r0, unsigned& r1,
                                      unsigned& r2, unsigned& r3) {
    asm volatile("ldmatrix.sync.aligned.m8n8.x4.shared.b16 {%0, %1, %2, %3}, [%4];"
                 : "=r"(r0), "=r"(r1), "=r"(r2), "=r"(r3) : "r"(addr));
}
__device__ __forceinline__ void mma16816(float* c,
                                         unsigned a0, unsigned a1, unsigned a2, unsigned a3,
                                         unsigned b0, unsigned b1) {
    asm volatile("mma.sync.aligned.m16n8k16.row.col.f32.f16.f16.f32 "
                 "{%0,%1,%2,%3}, {%4,%5,%6,%7}, {%8,%9}, {%0,%1,%2,%3};"
                 : "+f"(c[0]), "+f"(c[1]), "+f"(c[2]), "+f"(c[3])
                 : "r"(a0), "r"(a1), "r"(a2), "r"(a3), "r"(b0), "r"(b1));
}
__device__ __forceinline__ void cp16(unsigned dst, const void* src) {
    asm volatile("cp.async.cg.shared.global [%0], [%1], 16;" :: "r"(dst), "l"(src) : "memory");
}

// ---- pre-kernel: W (g,o,i,k) f32 -> (g,k,o,i) fp16 ----
__global__ void prep_w(const float* __restrict__ w) {
    int idx = blockIdx.x * 256 + threadIdx.x;
    if (idx >= Gg * KK * OPG * IPG) return;
    int i = idx & 63;
    int r = idx >> 6;
    int o = r & 63;
    int r2 = r >> 6;
    int k = r2 % KK;
    int g = r2 / KK;
    float v = w[(((g * OPG + o) * IPG + i) * KK) + k];
    g_Wh[idx] = __float2half_rn(v);
}

// stage W slice k into B buffer via cp.async; one commit_group
__device__ __forceinline__ void stage_B_async(unsigned smb, int buf, int k, int g, int tid) {
    const char* wh = (const char*)(g_Wh + (size_t)(g * KK + k) * (OPG * IPG));
    unsigned base = smb + SB + buf * B_BUF;
#pragma unroll
    for (int t = 0; t < 4; t++) {
        int ch = tid + t * 128;                // 512 x 16B chunks
        unsigned sw = sw128((unsigned)ch * 16);
        cp16(base + sw, wh + (size_t)ch * 16);
    }
    asm volatile("cp.async.commit_group;" ::: "memory");
}

__global__ __launch_bounds__(128, 4)
void masked_conv1d_hmma(const float* __restrict__ x,
                        const int*   __restrict__ pos,
                        float*       __restrict__ out) {
    extern __shared__ char sm[];
    const unsigned smb = smem_u32(sm);
    const int l0 = blockIdx.x * TL, g = blockIdx.y, b = blockIdx.z;
    const int tid = threadIdx.x;
    const int wid = tid >> 5, lane = tid & 31;

    // kick off W slice 0 immediately
    stage_B_async(smb, 0, 0, g, tid);

    const int lane8 = lane & 7, seg = lane >> 3;
    const int rbase = wid * 32 + (lane >> 2);        // this thread's base output row

    // ---- per-thread mask bits: bit(ci*5+k) = mask(row rbase+ci*8, conv-k) ----
    unsigned mbits = 0;
    {
        const int* pb = pos + b * Ll;
#pragma unroll
        for (int ci = 0; ci < 4; ci++) {
            int base = rbase + ci * 8;
            int glc = l0 + base;                      // center row, always in [0,Ll)
            int center = pb[glc] - glc;
#pragma unroll
            for (int k = 0; k < KK; k++) {
                int gl = l0 + base + k - 2;
                int d = (gl >= 0 && gl < Ll) ? (pb[gl] - gl) : 0x40000000;
                if (d == center) mbits |= 1u << (ci * 5 + k);
            }
        }
    }

    // ---- stage X tile: f32 -> fp16 hi/lo, swizzled 128B rows ----
    const float* xg = x + (size_t)b * Ll * Cc + g * IPG;
    for (int idx = tid; idx < A_ROWS * 16; idx += 128) {
        int j  = idx >> 4;
        int i4 = idx & 15;
        int gl = l0 - 2 + j;
        float4 v = make_float4(0.f, 0.f, 0.f, 0.f);
        if (gl >= 0 && gl < Ll)
            v = *(const float4*)(xg + (size_t)gl * Cc + i4 * 4);
        unsigned h0, h1, e0, e1;
        hilo2h(v.x, v.y, h0, e0);
        hilo2h(v.z, v.w, h1, e1);
        unsigned sw = sw128((unsigned)(j * 128 + i4 * 8));
        sts64(smb + SA_H + sw, h0, h1);
        sts64(smb + SA_L + sw, e0, e1);
    }

    // ---- accumulators: 2 M-tiles x 8 N-tiles x 4 ----
    float c[2][8][4];
#pragma unroll
    for (int mt = 0; mt < 2; mt++)
#pragma unroll
        for (int nt = 0; nt < 8; nt++)
#pragma unroll
            for (int e = 0; e < 4; e++) c[mt][nt][e] = 0.f;

    const unsigned acoff = (unsigned)((seg >> 1) << 3);
    const unsigned brow  = (unsigned)(lane8 + ((seg >> 1) << 3));
    const unsigned bcoff = (unsigned)((seg & 1) << 3);

#pragma unroll
    for (int k = 0; k < KK; k++) {
        asm volatile("cp.async.wait_group 0;" ::: "memory");
        __syncthreads();                 // W(k) visible; buf (k+1)&1 free (compute k-1 done)
        if (k < KK - 1) stage_B_async(smb, (k + 1) & 1, k + 1, g, tid);
        const unsigned bbase = smb + SB + (k & 1) * B_BUF;

        const bool m0 = (mbits >> (0 * 5 + k)) & 1;
        const bool m1 = (mbits >> (1 * 5 + k)) & 1;
        const bool m2 = (mbits >> (2 * 5 + k)) & 1;
        const bool m3 = (mbits >> (3 * 5 + k)) & 1;

        const unsigned arow0 = (unsigned)(wid * 32 + k + lane8 + ((seg & 1) << 3));

#pragma unroll
        for (int q = 0; q < 4; q++) {                  // 16-wide i-chunks
            unsigned ah[8], al[8];
            unsigned a0 = smb + SA_H + sw128(arow0 * 128 + (q * 16 + acoff) * 2);
            unsigned a1 = smb + SA_H + sw128((arow0 + 16) * 128 + (q * 16 + acoff) * 2);
            ldsm4(a0, ah[0], ah[1], ah[2], ah[3]);
            ldsm4(a1, ah[4], ah[5], ah[6], ah[7]);
            ldsm4(a0 + (SA_L - SA_H), al[0], al[1], al[2], al[3]);
            ldsm4(a1 + (SA_L - SA_H), al[4], al[5], al[6], al[7]);
            // row-granular mask
            ah[0] = m0 ? ah[0] : 0u;  ah[2] = m0 ? ah[2] : 0u;
            ah[1] = m1 ? ah[1] : 0u;  ah[3] = m1 ? ah[3] : 0u;
            ah[4] = m2 ? ah[4] : 0u;  ah[6] = m2 ? ah[6] : 0u;
            ah[5] = m3 ? ah[5] : 0u;  ah[7] = m3 ? ah[7] : 0u;
            al[0] = m0 ? al[0] : 0u;  al[2] = m0 ? al[2] : 0u;
            al[1] = m1 ? al[1] : 0u;  al[3] = m1 ? al[3] : 0u;
            al[4] = m2 ? al[4] : 0u;  al[6] = m2 ? al[6] : 0u;
            al[5] = m3 ? al[5] : 0u;  al[7] = m3 ? al[7] : 0u;

#pragma unroll
            for (int p = 0; p < 4; p++) {              // pairs of N-tiles
                unsigned baddr = bbase + sw128((p * 16 + brow) * 128 + (q * 16 + bcoff) * 2);
                unsigned bh0, bh1, bh2, bh3;
                ldsm4(baddr, bh0, bh1, bh2, bh3);
#pragma unroll
                for (int mt = 0; mt < 2; mt++) {
                    mma16816(c[mt][p*2],   ah[mt*4], ah[mt*4+1], ah[mt*4+2], ah[mt*4+3], bh0, bh1);
                    mma16816(c[mt][p*2+1], ah[mt*4], ah[mt*4+1], ah[mt*4+2], ah[mt*4+3], bh2, bh3);
                    mma16816(c[mt][p*2],   al[mt*4], al[mt*4+1], al[mt*4+2], al[mt*4+3], bh0, bh1);
                    mma16816(c[mt][p*2+1], al[mt*4], al[mt*4+1], al[mt*4+2], al[mt*4+3], bh2, bh3);
                }
            }
        }
    }

    // ---- epilogue: fragments -> out (B,L,G,OPG) ----
    const int ocol = (lane & 3) * 2;
#pragma unroll
    for (int mt = 0; mt < 2; mt++) {
        const int row0 = l0 + wid * 32 + mt * 16 + (lane >> 2);
        float* o0 = out + (((size_t)b * Ll + row0) * Gg + g) * OPG + ocol;
        float* o1 = o0 + (size_t)8 * Gg * OPG;
#pragma unroll
        for (int nt = 0; nt < 8; nt++) {
            *(float2*)(o0 + nt * 8) = make_float2(c[mt][nt][0], c[mt][nt][1]);
            *(float2*)(o1 + nt * 8) = make_float2(c[mt][nt][2], c[mt][nt][3]);
        }
    }
}

extern "C" void kernel_launch(void* const* d_in, const int* in_sizes, int n_in,
                              void* d_out, int out_size) {
    const float* x   = (const float*)d_in[0];
    const int*   pos = (const int*)d_in[1];
    const float* w   = (const float*)d_in[2];
    float*       out = (float*)d_out;

    prep_w<<<(Gg * KK * OPG * IPG + 255) / 256, 256>>>(w);

    cudaFuncSetAttribute(masked_conv1d_hmma,
                         cudaFuncAttributeMaxDynamicSharedMemorySize, SMEM_BYTES);
    dim3 grid(Ll / TL, Gg, Bb);   // (32, 16, 4)
    masked_conv1d_hmma<<<grid, 128, SMEM_BYTES>>>(x, pos, out);
}

// round 7
// speedup vs baseline: 1.8269x; 1.2048x over previous
#include <cuda_runtime.h>
#include <cuda_fp16.h>

// out[b,l,g,o] = sum_k mask(b,l,k) * sum_i X[b,l+k-2,g*64+i] * W[g,o,i,k]
// mask(l,k) = (pos[l+k-2]-(l+k-2) == pos[l]-l); X zero-padded outside [0,L).
// Single-pass fp16: X and W rounded once to fp16, fp32 accumulate.
//   rel_err ~ sqrt(2)*2^-12 ~ 3e-4  (threshold 1e-3)
// mma.sync m16n8k16 f32.f16.f16.f32; warp tile M=32xN=64; 4 CTAs/SM.

constexpr int Bb = 4, Ll = 4096, Cc = 1024, Gg = 16, IPG = 64, OPG = 64, KK = 5, TL = 128;
constexpr int A_ROWS = TL + 4;    // 132

// pre-rounded W: [g][k][o][i] fp16
__device__ __half g_Wh[Gg * KK * OPG * IPG];

// smem layout (bytes); 128B rows, SW128 swizzled
constexpr int SA    = 0;                       // A: 132 x 128B = 16896
constexpr int SB    = A_ROWS * 128;            // 16896: W double buffer
constexpr int B_BUF = 8192;                    // one k-slice (64x64 fp16)
constexpr int SMEM_BYTES = SB + 2 * B_BUF;     // 33280 -> 4 CTAs/SM (reg-bound)

__device__ __forceinline__ unsigned smem_u32(const void* p) {
    unsigned a;
    asm("{ .reg .u64 t; cvta.to.shared.u64 t, %1; cvt.u32.u64 %0, t; }" : "=r"(a) : "l"(p));
    return a;
}
__device__ __forceinline__ unsigned sw128(unsigned off) { return off ^ ((off >> 3) & 0x70); }

__device__ __forceinline__ void sts64(unsigned addr, unsigned r0, unsigned r1) {
    asm volatile("st.shared.v2.b32 [%0], {%1, %2};" :: "r"(addr), "r"(r0), "r"(r1) : "memory");
}
__device__ __forceinline__ void ldsm4(unsigned addr, unsigned& r0, unsigned& r1,
                                      unsigned& r2, unsigned& r3) {
    asm volatile("ldmatrix.sync.aligned.m8n8.x4.shared.b16 {%0, %1, %2, %3}, [%4];"
                 : "=r"(r0), "=r"(r1), "=r"(r2), "=r"(r3) : "r"(addr));
}
__device__ __forceinline__ void mma16816(float* c,
                                         unsigned a0, unsigned a1, unsigned a2, unsigned a3,
                                         unsigned b0, unsigned b1) {
    asm volatile("mma.sync.aligned.m16n8k16.row.col.f32.f16.f16.f32 "
                 "{%0,%1,%2,%3}, {%4,%5,%6,%7}, {%8,%9}, {%0,%1,%2,%3};"
                 : "+f"(c[0]), "+f"(c[1]), "+f"(c[2]), "+f"(c[3])
                 : "r"(a0), "r"(a1), "r"(a2), "r"(a3), "r"(b0), "r"(b1));
}
__device__ __forceinline__ void cp16(unsigned dst, const void* src) {
    asm volatile("cp.async.cg.shared.global [%0], [%1], 16;" :: "r"(dst), "l"(src) : "memory");
}

// ---- pre-kernel: W (g,o,i,k) f32 -> (g,k,o,i) fp16 ----
__global__ void prep_w(const float* __restrict__ w) {
    int idx = blockIdx.x * 256 + threadIdx.x;
    if (idx >= Gg * KK * OPG * IPG) return;
    int i = idx & 63;
    int r = idx >> 6;
    int o = r & 63;
    int r2 = r >> 6;
    int k = r2 % KK;
    int g = r2 / KK;
    float v = w[(((g * OPG + o) * IPG + i) * KK) + k];
    g_Wh[idx] = __float2half_rn(v);
}

// stage W slice k into B buffer via cp.async; one commit_group
__device__ __forceinline__ void stage_B_async(unsigned smb, int buf, int k, int g, int tid) {
    const char* wh = (const char*)(g_Wh + (size_t)(g * KK + k) * (OPG * IPG));
    unsigned base = smb + SB + buf * B_BUF;
#pragma unroll
    for (int t = 0; t < 4; t++) {
        int ch = tid + t * 128;                // 512 x 16B chunks
        unsigned sw = sw128((unsigned)ch * 16);
        cp16(base + sw, wh + (size_t)ch * 16);
    }
    asm volatile("cp.async.commit_group;" ::: "memory");
}

__global__ __launch_bounds__(128, 4)
void masked_conv1d_hmma(const float* __restrict__ x,
                        const int*   __restrict__ pos,
                        float*       __restrict__ out) {
    extern __shared__ char sm[];
    const unsigned smb = smem_u32(sm);
    const int l0 = blockIdx.x * TL, g = blockIdx.y, b = blockIdx.z;
    const int tid = threadIdx.x;
    const int wid = tid >> 5, lane = tid & 31;

    // kick off W slice 0 immediately
    stage_B_async(smb, 0, 0, g, tid);

    const int lane8 = lane & 7, seg = lane >> 3;
    const int rbase = wid * 32 + (lane >> 2);        // this thread's base output row

    // ---- per-thread mask bits: bit(ci*5+k) = mask(row rbase+ci*8, conv-k) ----
    unsigned mbits = 0;
    {
        const int* pb = pos + b * Ll;
#pragma unroll
        for (int ci = 0; ci < 4; ci++) {
            int base = rbase + ci * 8;
            int glc = l0 + base;                      // center row, always in [0,Ll)
            int center = pb[glc] - glc;
#pragma unroll
            for (int k = 0; k < KK; k++) {
                int gl = l0 + base + k - 2;
                int d = (gl >= 0 && gl < Ll) ? (pb[gl] - gl) : 0x40000000;
                if (d == center) mbits |= 1u << (ci * 5 + k);
            }
        }
    }

    // ---- stage X tile: f32 -> fp16, swizzled 128B rows ----
    const float* xg = x + (size_t)b * Ll * Cc + g * IPG;
    for (int idx = tid; idx < A_ROWS * 16; idx += 128) {
        int j  = idx >> 4;
        int i4 = idx & 15;
        int gl = l0 - 2 + j;
        float4 v = make_float4(0.f, 0.f, 0.f, 0.f);
        if (gl >= 0 && gl < Ll)
            v = *(const float4*)(xg + (size_t)gl * Cc + i4 * 4);
        unsigned h0, h1;
        asm("cvt.rn.f16x2.f32 %0, %1, %2;" : "=r"(h0) : "f"(v.y), "f"(v.x));
        asm("cvt.rn.f16x2.f32 %0, %1, %2;" : "=r"(h1) : "f"(v.w), "f"(v.z));
        unsigned sw = sw128((unsigned)(j * 128 + i4 * 8));
        sts64(smb + SA + sw, h0, h1);
    }

    // ---- accumulators: 2 M-tiles x 8 N-tiles x 4 ----
    float c[2][8][4];
#pragma unroll
    for (int mt = 0; mt < 2; mt++)
#pragma unroll
        for (int nt = 0; nt < 8; nt++)
#pragma unroll
            for (int e = 0; e < 4; e++) c[mt][nt][e] = 0.f;

    const unsigned acoff = (unsigned)((seg >> 1) << 3);
    const unsigned brow  = (unsigned)(lane8 + ((seg >> 1) << 3));
    const unsigned bcoff = (unsigned)((seg & 1) << 3);

#pragma unroll
    for (int k = 0; k < KK; k++) {
        asm volatile("cp.async.wait_group 0;" ::: "memory");
        __syncthreads();                 // W(k) visible; buf (k+1)&1 free (compute k-1 done)
        if (k < KK - 1) stage_B_async(smb, (k + 1) & 1, k + 1, g, tid);
        const unsigned bbase = smb + SB + (k & 1) * B_BUF;

        const bool m0 = (mbits >> (0 * 5 + k)) & 1;
        const bool m1 = (mbits >> (1 * 5 + k)) & 1;
        const bool m2 = (mbits >> (2 * 5 + k)) & 1;
        const bool m3 = (mbits >> (3 * 5 + k)) & 1;

        const unsigned arow0 = (unsigned)(wid * 32 + k + lane8 + ((seg & 1) << 3));

#pragma unroll
        for (int q = 0; q < 4; q++) {                  // 16-wide i-chunks
            unsigned ah[8];
            unsigned a0 = smb + SA + sw128(arow0 * 128 + (q * 16 + acoff) * 2);
            unsigned a1 = smb + SA + sw128((arow0 + 16) * 128 + (q * 16 + acoff) * 2);
            ldsm4(a0, ah[0], ah[1], ah[2], ah[3]);
            ldsm4(a1, ah[4], ah[5], ah[6], ah[7]);
            // row-granular mask
            ah[0] = m0 ? ah[0] : 0u;  ah[2] = m0 ? ah[2] : 0u;
            ah[1] = m1 ? ah[1] : 0u;  ah[3] = m1 ? ah[3] : 0u;
            ah[4] = m2 ? ah[4] : 0u;  ah[6] = m2 ? ah[6] : 0u;
            ah[5] = m3 ? ah[5] : 0u;  ah[7] = m3 ? ah[7] : 0u;

#pragma unroll
            for (int p = 0; p < 4; p++) {              // pairs of N-tiles
                unsigned baddr = bbase + sw128((p * 16 + brow) * 128 + (q * 16 + bcoff) * 2);
                unsigned bh0, bh1, bh2, bh3;
                ldsm4(baddr, bh0, bh1, bh2, bh3);
#pragma unroll
                for (int mt = 0; mt < 2; mt++) {
                    mma16816(c[mt][p*2],   ah[mt*4], ah[mt*4+1], ah[mt*4+2], ah[mt*4+3], bh0, bh1);
                    mma16816(c[mt][p*2+1], ah[mt*4], ah[mt*4+1], ah[mt*4+2], ah[mt*4+3], bh2, bh3);
                }
            }
        }
    }

    // ---- epilogue: fragments -> out (B,L,G,OPG) ----
    const int ocol = (lane & 3) * 2;
#pragma unroll
    for (int mt = 0; mt < 2; mt++) {
        const int row0 = l0 + wid * 32 + mt * 16 + (lane >> 2);
        float* o0 = out + (((size_t)b * Ll + row0) * Gg + g) * OPG + ocol;
        float* o1 = o0 + (size_t)8 * Gg * OPG;
#pragma unroll
        for (int nt = 0; nt < 8; nt++) {
            *(float2*)(o0 + nt * 8) = make_float2(c[mt][nt][0], c[mt][nt][1]);
            *(float2*)(o1 + nt * 8) = make_float2(c[mt][nt][2], c[mt][nt][3]);
        }
    }
}

extern "C" void kernel_launch(void* const* d_in, const int* in_sizes, int n_in,
                              void* d_out, int out_size) {
    const float* x   = (const float*)d_in[0];
    const int*   pos = (const int*)d_in[1];
    const float* w   = (const float*)d_in[2];
    float*       out = (float*)d_out;

    prep_w<<<(Gg * KK * OPG * IPG + 255) / 256, 256>>>(w);

    cudaFuncSetAttribute(masked_conv1d_hmma,
                         cudaFuncAttributeMaxDynamicSharedMemorySize, SMEM_BYTES);
    dim3 grid(Ll / TL, Gg, Bb);   // (32, 16, 4)
    masked_conv1d_hmma<<<grid, 128, SMEM_BYTES>>>(x, pos, out);
}